// round 14
// baseline (speedup 1.0000x reference)
#include <cuda_runtime.h>
#include <cuda_bf16.h>
#include <cstdint>
#include <cstddef>

#define T_STEPS 100
#define BATCH   256
#define HID     1024
#define N_IN    4096

#define NCTA    128
#define THREADS 512
#define GROUPS  8          // batch groups (32 rows each)
#define GSZ     16         // CTAs per group (N tiles)
#define MT      32         // batch rows per group
#define NT      64         // hidden cols per CTA
#define KC      256        // K chunk per warpgroup
#define SW      1032       // A smem row stride in bf16 (conflict-free ldmatrix)
#define XW      68         // xs row stride in floats
#define RSTRIDE 20         // red row stride in floats (16B-aligned, conflict-free)
#define REDSZ   (3 * 128 * RSTRIDE)   // floats per red buffer
#define FPAD    32         // ints per flag (own 128B line)

// ---------------- device scratch ----------------
__device__ __nv_bfloat16 g_hidden[(size_t)(T_STEPS + 1) * BATCH * HID];
__device__ float         g_WxT[(size_t)N_IN * HID];             // Wx^T with (bm+bx) folded
__device__ int           g_flag[(T_STEPS + 1) * GROUPS * GSZ * FPAD]; // 1 producer each
__device__ unsigned      g_count;                               // full-grid barrier
__device__ unsigned      g_gen;

// ---------------- helpers ----------------
__device__ __forceinline__ uint32_t smem_u32(const void* p) {
    return (uint32_t)__cvta_generic_to_shared(p);
}
__device__ __forceinline__ void ldmx4(uint32_t& r0, uint32_t& r1, uint32_t& r2, uint32_t& r3,
                                      uint32_t addr) {
    asm volatile("ldmatrix.sync.aligned.m8n8.x4.shared.b16 {%0,%1,%2,%3},[%4];\n"
                 : "=r"(r0), "=r"(r1), "=r"(r2), "=r"(r3) : "r"(addr));
}
__device__ __forceinline__ void mma16816(float* c, uint32_t a0, uint32_t a1, uint32_t a2,
                                         uint32_t a3, uint32_t b0, uint32_t b1) {
    asm volatile("mma.sync.aligned.m16n8k16.row.col.f32.bf16.bf16.f32 "
                 "{%0,%1,%2,%3},{%4,%5,%6,%7},{%8,%9},{%0,%1,%2,%3};\n"
                 : "+f"(c[0]), "+f"(c[1]), "+f"(c[2]), "+f"(c[3])
                 : "r"(a0), "r"(a1), "r"(a2), "r"(a3), "r"(b0), "r"(b1));
}
__device__ __forceinline__ void cp16(uint32_t dst, const void* src) {
    asm volatile("cp.async.cg.shared.global [%0],[%1],16;\n" :: "r"(dst), "l"(src));
}
__device__ __forceinline__ int ld_acq(const int* p) {
    int v;
    asm volatile("ld.acquire.gpu.global.b32 %0,[%1];" : "=r"(v) : "l"(p) : "memory");
    return v;
}
__device__ __forceinline__ void st_rel(int* p, int v) {
    asm volatile("st.release.gpu.global.u32 [%0], %1;" :: "l"(p), "r"(v) : "memory");
}
__device__ __forceinline__ void bar_sync(int id, int cnt) {
    asm volatile("bar.sync %0, %1;" :: "r"(id), "r"(cnt) : "memory");
}
__device__ __forceinline__ void bar_arrive(int id, int cnt) {
    asm volatile("bar.arrive %0, %1;" :: "r"(id), "r"(cnt) : "memory");
}

__device__ __forceinline__ void grid_barrier(int tid) {
    __syncthreads();
    if (tid == 0) {
        __threadfence();
        unsigned gen = atomicAdd(&g_gen, 0u);
        unsigned old = atomicAdd(&g_count, 1u);
        if (old == NCTA - 1) {
            atomicExch(&g_count, 0u);
            __threadfence();
            atomicAdd(&g_gen, 1u);
        } else {
            while (*(volatile unsigned*)&g_gen == gen) { }
        }
        __threadfence();
    }
    __syncthreads();
}

// poll one producer flag, broadcast to warpgroup, issue the 64-col mini-chunk load
#define POLL_ISSUE(c) do {                                                        \
    if (t > 0) {                                                                  \
        if (wtid == 0) {                                                          \
            const int* f = &g_flag[fbase + (c) * FPAD];                           \
            while (ld_acq(f) != 1) { }                                            \
        }                                                                         \
        bar_sync(1 + wg, 128);                                                    \
    }                                                                             \
    {                                                                             \
        int c8a = wg * 32 + (c) * 8 + cp_q4 * 2;                                  \
        cp16(cp_dst_row + (uint32_t)(c8a * 16), rowp + c8a * 8);                  \
        cp16(cp_dst_row + (uint32_t)((c8a + 1) * 16), rowp + (c8a + 1) * 8);      \
        asm volatile("cp.async.commit_group;" ::: "memory");                      \
    }                                                                             \
} while (0)

// wait for mini-chunk (c), then MMA its 4 k-steps
#define MMA_BLOCK(c, wn) do {                                                     \
    asm volatile("cp.async.wait_group %0;" :: "n"(wn) : "memory");                \
    bar_sync(1 + wg, 128);                                                        \
    _Pragma("unroll")                                                             \
    for (int kk = (c) * 4; kk < (c) * 4 + 4; kk++) {                              \
        const uint32_t kbyte = (uint32_t)((wg * KC + kk * 16) * 2);               \
        uint32_t a0, a1, a2, a3, a4, a5, a6, a7;                                  \
        ldmx4(a0, a1, a2, a3, a_lane + kbyte);                                    \
        ldmx4(a4, a5, a6, a7, a_lane + (uint32_t)(16 * SW * 2) + kbyte);          \
        mma16816(acc[0][0], a0, a1, a2, a3, breg[kk][0], breg[kk][1]);            \
        mma16816(acc[0][1], a0, a1, a2, a3, breg[kk][2], breg[kk][3]);            \
        mma16816(acc[1][0], a4, a5, a6, a7, breg[kk][0], breg[kk][1]);            \
        mma16816(acc[1][1], a4, a5, a6, a7, breg[kk][2], breg[kk][3]);            \
    }                                                                             \
} while (0)

// ---------------- single fused persistent kernel ----------------
__global__ void __launch_bounds__(THREADS, 1) rnn_kernel(
    const int* __restrict__ x_idx, const int* __restrict__ y_idx,
    const float* __restrict__ truth, const float* __restrict__ Wm,
    const float* __restrict__ bm, const float* __restrict__ Wx,
    const float* __restrict__ bx, const float* __restrict__ Wy,
    const float* __restrict__ by, const float* __restrict__ b_start,
    float* __restrict__ out) {
    extern __shared__ __align__(16) char smem_raw[];
    __nv_bfloat16* a_s = (__nv_bfloat16*)smem_raw;        // 32 x SW bf16 (full h tile)
    float*         xs  = (float*)(a_s + MT * SW);         // 32 x XW floats (+xpose stage)
    float*         red = xs + MT * XW;                    // 2 x REDSZ floats (dbuf partials)

    const int tid  = threadIdx.x;
    const int warp = tid >> 5, lane = tid & 31;
    const int wg   = warp >> 2;        // K chunk this warpgroup owns (0..3)
    const int nw   = warp & 3;         // N16 subtile within CTA (0..3)
    const int wtid = tid & 127;
    const int grp = blockIdx.x >> 4;   // batch group (8)
    const int nt  = blockIdx.x & 15;   // N tile within group (16)
    const int m0 = grp * MT;
    const int n0 = nt * NT;

    // ---- prologue: h0 = b_start broadcast ----
    for (int i = tid; i < MT * (NT / 2); i += THREADS) {
        int r = i >> 5, c2 = i & 31;
        __nv_bfloat162 v = __floats2bfloat162_rn(b_start[n0 + c2 * 2],
                                                 b_start[n0 + c2 * 2 + 1]);
        *(__nv_bfloat162*)&g_hidden[(size_t)(m0 + r) * HID + n0 + c2 * 2] = v;
    }

    // ---- prologue: transpose Wx slice with (bm+bx) folded ----
    {
        float (*tile)[33] = (float (*)[33])xs;
        int x0 = blockIdx.x * 32;
        int tx = lane, ty = warp;        // 32 x 16
        for (int yt = 0; yt < HID / 32; yt++) {
            int y0 = yt * 32;
            for (int i = ty; i < 32; i += 16)
                tile[i][tx] = Wx[(size_t)(y0 + i) * N_IN + x0 + tx];
            __syncthreads();
            for (int i = ty; i < 32; i += 16)
                g_WxT[(size_t)(x0 + i) * HID + y0 + tx] = tile[tx][i] + bm[y0 + tx] + bx[y0 + tx];
            __syncthreads();
        }
    }

    // ---- prologue: preload B fragments (Wm) into registers, ONCE ----
    uint32_t breg[16][4];
    {
        const int nb = n0 + nw * 16 + (lane >> 2);
        const int kb = wg * KC + (lane & 3) * 2;
        #pragma unroll
        for (int kk = 0; kk < 16; kk++) {
            #pragma unroll
            for (int j = 0; j < 4; j++) {
                const float2 v = *(const float2*)&Wm[(size_t)(nb + (j >> 1) * 8) * HID
                                                     + kb + kk * 16 + (j & 1) * 8];
                ((__nv_bfloat162*)&breg[kk][j])[0] = __floats2bfloat162_rn(v.x, v.y);
            }
        }
    }
    __threadfence();
    grid_barrier(tid);   // WxT + h0 visible everywhere

    // A ldmatrix lane base (row = lane&15, k-half = lane>>4)
    const uint32_t a_lane = smem_u32(a_s) +
        (uint32_t)(((lane & 15) * SW + ((lane >> 4) << 3)) * 2);
    const int cp_row = wtid >> 2, cp_q4 = wtid & 3;
    const uint32_t cp_dst_row = smem_u32(a_s) + (uint32_t)(cp_row * SW * 2);

    // ---- mainloop: per-producer mini-chunk dataflow (skew-absorbing pipeline) ----
    for (int t = 0; t < T_STEPS; t++) {
        // wg0 gathers x projection (it alone runs the epilogue)
        if (wg == 0) {
            const int r = wtid >> 2, seg = wtid & 3;
            int x = x_idx[t * BATCH + m0 + r];
            const float4* src = (const float4*)&g_WxT[(size_t)x * HID + n0 + seg * 16];
            float4* dst = (float4*)&xs[r * XW + seg * 16];
            dst[0] = src[0]; dst[1] = src[1]; dst[2] = src[2]; dst[3] = src[3];
        }

        const __nv_bfloat16* rowp = g_hidden + (size_t)t * BATCH * HID
                                  + (size_t)(m0 + cp_row) * HID;
        const int fbase = ((t * GROUPS + grp) * GSZ + wg * 4) * FPAD;

        float acc[2][2][4];
        #pragma unroll
        for (int i = 0; i < 2; i++)
            #pragma unroll
            for (int j = 0; j < 2; j++)
                acc[i][j][0] = acc[i][j][1] = acc[i][j][2] = acc[i][j][3] = 0.f;

        // interleaved: poll/issue each 64-col mini on its SINGLE producer; MMA overlaps
        POLL_ISSUE(0);
        POLL_ISSUE(1);
        MMA_BLOCK(0, 1);
        POLL_ISSUE(2);
        MMA_BLOCK(1, 1);
        POLL_ISSUE(3);
        MMA_BLOCK(2, 1);
        MMA_BLOCK(3, 0);

        float* af = &acc[0][0][0];
        float* rbuf = red + (t & 1) * REDSZ;
        if (wg != 0) {
            // publish partials (aligned float4, conflict-free stride 20) and run ahead
            float4* dst = (float4*)&rbuf[((wg - 1) * 128 + wtid) * RSTRIDE];
            #pragma unroll
            for (int q = 0; q < 4; q++) dst[q] = ((const float4*)af)[q];
            bar_arrive(5, THREADS);
        } else {
            bar_sync(5, THREADS);   // wait for wgs 1-3 partials
            #pragma unroll
            for (int p = 0; p < 3; p++) {
                const float4* src = (const float4*)&rbuf[(p * 128 + wtid) * RSTRIDE];
                #pragma unroll
                for (int q = 0; q < 4; q++) {
                    float4 v = src[q];
                    af[q * 4 + 0] += v.x; af[q * 4 + 1] += v.y;
                    af[q * 4 + 2] += v.z; af[q * 4 + 3] += v.w;
                }
            }

            // epilogue: + xproj(+bias), tanh.approx, pack bf16, store h[t+1]
            __nv_bfloat16* hout = g_hidden + (size_t)(t + 1) * BATCH * HID;
            const int r_base = lane >> 2;
            const int c_base = (lane & 3) * 2;
            #pragma unroll
            for (int mi = 0; mi < 2; mi++) {
                #pragma unroll
                for (int ni = 0; ni < 2; ni++) {
                    int col = nw * 16 + ni * 8 + c_base;
                    #pragma unroll
                    for (int half = 0; half < 2; half++) {
                        int row = mi * 16 + r_base + half * 8;
                        float v0 = acc[mi][ni][half * 2 + 0] + xs[row * XW + col];
                        float v1 = acc[mi][ni][half * 2 + 1] + xs[row * XW + col + 1];
                        asm("tanh.approx.f32 %0, %0;" : "+f"(v0));
                        asm("tanh.approx.f32 %0, %0;" : "+f"(v1));
                        *(__nv_bfloat162*)&hout[(size_t)(m0 + row) * HID + n0 + col] =
                            __floats2bfloat162_rn(v0, v1);
                    }
                }
            }
            bar_sync(6, 128);       // wg0 stores complete (also orders next xs gather)
            if (wtid == 0) {
                // single-writer flag: release store (bar6 gives cumulativity over wg0 stores)
                st_rel(&g_flag[(((t + 1) * GROUPS + grp) * GSZ + nt) * FPAD], 1);
            }
        }
    }

    // ---- fused logits / pred / loss ----
    if (tid == 0) {
        const int base = (T_STEPS * GROUPS + grp) * GSZ;
        for (int c = 0; c < GSZ; c++)
            while (ld_acq(&g_flag[(base + c) * FPAD]) != 1) { }
    }
    __syncthreads();

    for (int i = 0; i < 13; i++) {
        int j = i * 16 + warp;               // 200 samples per CTA
        if (j >= 200) break;
        int jj = nt * 200 + j;
        int t  = jj >> 5;
        int bl = jj & 31;
        int gw = t * BATCH + m0 + bl;
        int y  = y_idx[gw];
        const __nv_bfloat16* h = g_hidden + (size_t)(t + 1) * BATCH * HID
                               + (size_t)(m0 + bl) * HID;
        const float* wy = Wy + (size_t)y * HID;
        float acc = 0.f;
        #pragma unroll
        for (int p = 0; p < 4; p++) {
            int k = p * 256 + lane * 8;
            uint4 hv = *(const uint4*)(h + k);
            const float4* w4 = (const float4*)(wy + k);
            float4 w0 = w4[0], w1 = w4[1];
            const __nv_bfloat162* hb = (const __nv_bfloat162*)&hv;
            float2 f0 = __bfloat1622float2(hb[0]);
            float2 f1 = __bfloat1622float2(hb[1]);
            float2 f2 = __bfloat1622float2(hb[2]);
            float2 f3 = __bfloat1622float2(hb[3]);
            acc += f0.x * w0.x + f0.y * w0.y + f1.x * w0.z + f1.y * w0.w
                 + f2.x * w1.x + f2.y * w1.y + f3.x * w1.z + f3.y * w1.w;
        }
        #pragma unroll
        for (int o = 16; o; o >>= 1) acc += __shfl_xor_sync(0xffffffffu, acc, o);
        if (lane == 0) {
            float logit = acc + by[y];
            float pred = 1.f / (1.f + expf(-logit));
            float tr = truth[gw];
            float lsp = fminf(logit, 0.f)  - log1pf(expf(-fabsf(logit)));
            float lsn = fminf(-logit, 0.f) - log1pf(expf(-fabsf(logit)));
            out[gw] = pred;
            out[T_STEPS * BATCH + gw] = -(tr * lsp + (1.f - tr) * lsn);
        }
    }

    // ---- reset flags for the next graph replay ----
    grid_barrier(tid);     // nobody still polling
    for (int i = blockIdx.x * THREADS + tid; i < (T_STEPS + 1) * GROUPS * GSZ * FPAD;
         i += NCTA * THREADS)
        g_flag[i] = 0;
    __threadfence();
    grid_barrier(tid);     // resets visible before exit
}

// ---------------- launch ----------------
extern "C" void kernel_launch(void* const* d_in, const int* in_sizes, int n_in,
                              void* d_out, int out_size) {
    (void)in_sizes; (void)n_in; (void)out_size;
    const int*   x_idx   = (const int*)d_in[0];
    const int*   y_idx   = (const int*)d_in[1];
    const float* truth   = (const float*)d_in[2];
    const float* Wm      = (const float*)d_in[3];
    const float* bm      = (const float*)d_in[4];
    const float* Wx      = (const float*)d_in[5];
    const float* bx      = (const float*)d_in[6];
    const float* Wy      = (const float*)d_in[7];
    const float* by      = (const float*)d_in[8];
    // d_in[9] = W_start: multiplied by zeros -> unused
    const float* b_start = (const float*)d_in[10];
    float* out = (float*)d_out;

    // smem: A tile + xs + double-buffered reduction = ~135 KB
    const int smem_bytes = MT * SW * 2 + (MT * XW + 2 * REDSZ) * 4;
    cudaFuncSetAttribute(rnn_kernel, cudaFuncAttributeMaxDynamicSharedMemorySize, smem_bytes);
    rnn_kernel<<<NCTA, THREADS, smem_bytes>>>(x_idx, y_idx, truth, Wm, bm, Wx, bx,
                                              Wy, by, b_start, out);
}

// round 15
// speedup vs baseline: 1.0106x; 1.0106x over previous
#include <cuda_runtime.h>
#include <cuda_bf16.h>
#include <cstdint>
#include <cstddef>

#define T_STEPS 100
#define BATCH   256
#define HID     1024
#define N_IN    4096

#define NCTA    128
#define THREADS 512
#define GROUPS  8          // batch groups (32 rows each)
#define GSZ     16         // CTAs per group (N tiles)
#define MT      32         // batch rows per group
#define ST      16         // rows per stream (2 streams per group)
#define NT      64         // hidden cols per CTA
#define KC      256        // K chunk per warpgroup
#define SW      1032       // A smem row stride in bf16 (conflict-free ldmatrix)
#define XW      68         // xs row stride in floats
#define RST2    12         // partial stride in floats (16B-aligned, conflict-free)
#define RED1    (3 * 128 * RST2)      // floats per (stream,parity) partial buffer

// ---------------- device scratch ----------------
__device__ __nv_bfloat16 g_hidden[(size_t)(T_STEPS + 1) * BATCH * HID];
__device__ float         g_WxT[(size_t)N_IN * HID];             // Wx^T with (bm+bx) folded
__device__ int           g_ready[(T_STEPS + 1) * GROUPS * 8];   // [t][grp][stream][chunk]
__device__ unsigned      g_count;                               // full-grid barrier
__device__ unsigned      g_gen;

// ---------------- helpers ----------------
__device__ __forceinline__ uint32_t smem_u32(const void* p) {
    return (uint32_t)__cvta_generic_to_shared(p);
}
__device__ __forceinline__ void ldmx4(uint32_t& r0, uint32_t& r1, uint32_t& r2, uint32_t& r3,
                                      uint32_t addr) {
    asm volatile("ldmatrix.sync.aligned.m8n8.x4.shared.b16 {%0,%1,%2,%3},[%4];\n"
                 : "=r"(r0), "=r"(r1), "=r"(r2), "=r"(r3) : "r"(addr));
}
__device__ __forceinline__ void mma16816(float* c, uint32_t a0, uint32_t a1, uint32_t a2,
                                         uint32_t a3, uint32_t b0, uint32_t b1) {
    asm volatile("mma.sync.aligned.m16n8k16.row.col.f32.bf16.bf16.f32 "
                 "{%0,%1,%2,%3},{%4,%5,%6,%7},{%8,%9},{%0,%1,%2,%3};\n"
                 : "+f"(c[0]), "+f"(c[1]), "+f"(c[2]), "+f"(c[3])
                 : "r"(a0), "r"(a1), "r"(a2), "r"(a3), "r"(b0), "r"(b1));
}
__device__ __forceinline__ void cp16(uint32_t dst, const void* src) {
    asm volatile("cp.async.cg.shared.global [%0],[%1],16;\n" :: "r"(dst), "l"(src));
}
__device__ __forceinline__ int ld_acq(const int* p) {
    int v;
    asm volatile("ld.acquire.gpu.global.b32 %0,[%1];" : "=r"(v) : "l"(p) : "memory");
    return v;
}
__device__ __forceinline__ void bar_sync(int id, int cnt) {
    asm volatile("bar.sync %0, %1;" :: "r"(id), "r"(cnt) : "memory");
}
__device__ __forceinline__ void bar_arrive(int id, int cnt) {
    asm volatile("bar.arrive %0, %1;" :: "r"(id), "r"(cnt) : "memory");
}

__device__ __forceinline__ void grid_barrier(int tid) {
    __syncthreads();
    if (tid == 0) {
        __threadfence();
        unsigned gen = atomicAdd(&g_gen, 0u);
        unsigned old = atomicAdd(&g_count, 1u);
        if (old == NCTA - 1) {
            atomicExch(&g_count, 0u);
            __threadfence();
            atomicAdd(&g_gen, 1u);
        } else {
            while (*(volatile unsigned*)&g_gen == gen) { }
        }
        __threadfence();
    }
    __syncthreads();
}

// ---------------- single fused persistent kernel ----------------
__global__ void __launch_bounds__(THREADS, 1) rnn_kernel(
    const int* __restrict__ x_idx, const int* __restrict__ y_idx,
    const float* __restrict__ truth, const float* __restrict__ Wm,
    const float* __restrict__ bm, const float* __restrict__ Wx,
    const float* __restrict__ bx, const float* __restrict__ Wy,
    const float* __restrict__ by, const float* __restrict__ b_start,
    float* __restrict__ out) {
    extern __shared__ __align__(16) char smem_raw[];
    __nv_bfloat16* a_s = (__nv_bfloat16*)smem_raw;        // 2 x 16 x SW bf16 (stream A tiles)
    float*         xs  = (float*)(a_s + MT * SW);         // 32 x XW floats (+xpose stage)
    float*         red = xs + MT * XW;                    // 4 x RED1 floats (s x parity)

    const int tid  = threadIdx.x;
    const int warp = tid >> 5, lane = tid & 31;
    const int wg   = warp >> 2;        // K chunk this warpgroup owns (0..3)
    const int nw   = warp & 3;         // N16 subtile within CTA (0..3)
    const int wtid = tid & 127;
    const int grp = blockIdx.x >> 4;   // batch group (8)
    const int nt  = blockIdx.x & 15;   // N tile within group (16)
    const int m0 = grp * MT;
    const int n0 = nt * NT;

    // ---- prologue: h0 = b_start broadcast ----
    for (int i = tid; i < MT * (NT / 2); i += THREADS) {
        int r = i >> 5, c2 = i & 31;
        __nv_bfloat162 v = __floats2bfloat162_rn(b_start[n0 + c2 * 2],
                                                 b_start[n0 + c2 * 2 + 1]);
        *(__nv_bfloat162*)&g_hidden[(size_t)(m0 + r) * HID + n0 + c2 * 2] = v;
    }

    // ---- prologue: transpose Wx slice with (bm+bx) folded ----
    {
        float (*tile)[33] = (float (*)[33])xs;
        int x0 = blockIdx.x * 32;
        int tx = lane, ty = warp;        // 32 x 16
        for (int yt = 0; yt < HID / 32; yt++) {
            int y0 = yt * 32;
            for (int i = ty; i < 32; i += 16)
                tile[i][tx] = Wx[(size_t)(y0 + i) * N_IN + x0 + tx];
            __syncthreads();
            for (int i = ty; i < 32; i += 16)
                g_WxT[(size_t)(x0 + i) * HID + y0 + tx] = tile[tx][i] + bm[y0 + tx] + bx[y0 + tx];
            __syncthreads();
        }
    }

    // ---- prologue: preload B fragments (Wm) into registers, ONCE ----
    // warp covers N16 (cols n0+nw*16..+16) x K256 (cols wg*256..+256)
    uint32_t breg[16][4];
    {
        const int nb = n0 + nw * 16 + (lane >> 2);
        const int kb = wg * KC + (lane & 3) * 2;
        #pragma unroll
        for (int kk = 0; kk < 16; kk++) {
            #pragma unroll
            for (int j = 0; j < 4; j++) {
                const float2 v = *(const float2*)&Wm[(size_t)(nb + (j >> 1) * 8) * HID
                                                     + kb + kk * 16 + (j & 1) * 8];
                ((__nv_bfloat162*)&breg[kk][j])[0] = __floats2bfloat162_rn(v.x, v.y);
            }
        }
    }
    __threadfence();
    grid_barrier(tid);   // WxT + h0 visible everywhere

    // per-stream A ldmatrix lane base (row = lane&15 within 16-row tile, k-half = lane>>4)
    const uint32_t a_lane0 = smem_u32(a_s) +
        (uint32_t)(((lane & 15) * SW + ((lane >> 4) << 3)) * 2);
    const uint32_t a_lane1 = a_lane0 + (uint32_t)(ST * SW * 2);
    // cp.async mapping: 128 threads cover 16 rows x 512B (4 cp16 per thread)
    const int cp_row = wtid >> 3, cp_seg = wtid & 7;
    const int mych = nt >> 2;            // chunk this CTA's output belongs to

    // ---- mainloop: two interleaved independent streams ----
    for (int t = 0; t < T_STEPS; t++) {
        const __nv_bfloat16* hbase = g_hidden + (size_t)t * BATCH * HID;
        const int fbase = (t * GROUPS + grp) * 8;

        // wg0 gathers x projection for BOTH streams (bar9 of prev iter ordered xs reads)
        if (wg == 0) {
            #pragma unroll
            for (int s = 0; s < 2; s++) {
                int x = x_idx[t * BATCH + m0 + s * ST + cp_row];
                const float4* src = (const float4*)&g_WxT[(size_t)x * HID + n0 + cp_seg * 8];
                float4* dst = (float4*)&xs[(s * ST + cp_row) * XW + cp_seg * 8];
                dst[0] = src[0]; dst[1] = src[1];
            }
        }

        // poll + issue stream 0, then stream 1 (both loads in flight together)
        #pragma unroll
        for (int s = 0; s < 2; s++) {
            if (t > 0) {
                if (wtid == 0) {
                    const int* f = &g_ready[fbase + s * 4 + wg];
                    while (ld_acq(f) < 4) { }
                }
                bar_sync(1 + wg, 128);
            }
            const __nv_bfloat16* rowp = hbase + (size_t)(m0 + s * ST + cp_row) * HID;
            uint32_t dst = smem_u32(a_s) + (uint32_t)((s * ST + cp_row) * SW * 2)
                         + (uint32_t)((wg * 256 + cp_seg * 32) * 2);
            #pragma unroll
            for (int q = 0; q < 4; q++)
                cp16(dst + (uint32_t)(q * 16), rowp + wg * 256 + cp_seg * 32 + q * 8);
            asm volatile("cp.async.commit_group;" ::: "memory");
        }

        // ---------- stream 0: MMA + reduce + tail ----------
        float acc[2][4];
        #pragma unroll
        for (int i = 0; i < 2; i++)
            acc[i][0] = acc[i][1] = acc[i][2] = acc[i][3] = 0.f;

        asm volatile("cp.async.wait_group 1;" ::: "memory");
        bar_sync(1 + wg, 128);
        #pragma unroll
        for (int kk = 0; kk < 16; kk++) {
            const uint32_t kbyte = (uint32_t)((wg * KC + kk * 16) * 2);
            uint32_t a0, a1, a2, a3;
            ldmx4(a0, a1, a2, a3, a_lane0 + kbyte);
            mma16816(acc[0], a0, a1, a2, a3, breg[kk][0], breg[kk][1]);
            mma16816(acc[1], a0, a1, a2, a3, breg[kk][2], breg[kk][3]);
        }

        {
            float* af = &acc[0][0];
            float* rbuf = red + (0 * 2 + (t & 1)) * RED1;
            if (wg != 0) {
                float4* dst = (float4*)&rbuf[((wg - 1) * 128 + wtid) * RST2];
                dst[0] = ((const float4*)af)[0];
                dst[1] = ((const float4*)af)[1];
                bar_arrive(5, THREADS);
            } else {
                bar_sync(5, THREADS);
                #pragma unroll
                for (int p = 0; p < 3; p++) {
                    const float4* src = (const float4*)&rbuf[(p * 128 + wtid) * RST2];
                    float4 v0 = src[0], v1 = src[1];
                    af[0] += v0.x; af[1] += v0.y; af[2] += v0.z; af[3] += v0.w;
                    af[4] += v1.x; af[5] += v1.y; af[6] += v1.z; af[7] += v1.w;
                }
                __nv_bfloat16* hout = g_hidden + (size_t)(t + 1) * BATCH * HID;
                const int rb = lane >> 2, cb = (lane & 3) * 2;
                #pragma unroll
                for (int ni = 0; ni < 2; ni++) {
                    int col = nw * 16 + ni * 8 + cb;
                    #pragma unroll
                    for (int half = 0; half < 2; half++) {
                        int row = rb + half * 8;                 // stream-0 rows 0..15
                        float v0 = acc[ni][half * 2 + 0] + xs[row * XW + col];
                        float v1 = acc[ni][half * 2 + 1] + xs[row * XW + col + 1];
                        asm("tanh.approx.f32 %0, %0;" : "+f"(v0));
                        asm("tanh.approx.f32 %0, %0;" : "+f"(v1));
                        *(__nv_bfloat162*)&hout[(size_t)(m0 + row) * HID + n0 + col] =
                            __floats2bfloat162_rn(v0, v1);
                    }
                }
                bar_sync(8, 128);        // wg0 stores complete
                if (wtid == 0) {
                    __threadfence();
                    atomicAdd(&g_ready[((t + 1) * GROUPS + grp) * 8 + 0 * 4 + mych], 1);
                }
            }
        }

        // ---------- stream 1: MMA + reduce + tail ----------
        #pragma unroll
        for (int i = 0; i < 2; i++)
            acc[i][0] = acc[i][1] = acc[i][2] = acc[i][3] = 0.f;

        asm volatile("cp.async.wait_group 0;" ::: "memory");
        bar_sync(1 + wg, 128);
        #pragma unroll
        for (int kk = 0; kk < 16; kk++) {
            const uint32_t kbyte = (uint32_t)((wg * KC + kk * 16) * 2);
            uint32_t a0, a1, a2, a3;
            ldmx4(a0, a1, a2, a3, a_lane1 + kbyte);
            mma16816(acc[0], a0, a1, a2, a3, breg[kk][0], breg[kk][1]);
            mma16816(acc[1], a0, a1, a2, a3, breg[kk][2], breg[kk][3]);
        }

        {
            float* af = &acc[0][0];
            float* rbuf = red + (1 * 2 + (t & 1)) * RED1;
            if (wg != 0) {
                float4* dst = (float4*)&rbuf[((wg - 1) * 128 + wtid) * RST2];
                dst[0] = ((const float4*)af)[0];
                dst[1] = ((const float4*)af)[1];
                bar_arrive(6, THREADS);
            } else {
                bar_sync(6, THREADS);
                #pragma unroll
                for (int p = 0; p < 3; p++) {
                    const float4* src = (const float4*)&rbuf[(p * 128 + wtid) * RST2];
                    float4 v0 = src[0], v1 = src[1];
                    af[0] += v0.x; af[1] += v0.y; af[2] += v0.z; af[3] += v0.w;
                    af[4] += v1.x; af[5] += v1.y; af[6] += v1.z; af[7] += v1.w;
                }
                __nv_bfloat16* hout = g_hidden + (size_t)(t + 1) * BATCH * HID;
                const int rb = lane >> 2, cb = (lane & 3) * 2;
                #pragma unroll
                for (int ni = 0; ni < 2; ni++) {
                    int col = nw * 16 + ni * 8 + cb;
                    #pragma unroll
                    for (int half = 0; half < 2; half++) {
                        int row = ST + rb + half * 8;            // stream-1 rows 16..31
                        float v0 = acc[ni][half * 2 + 0] + xs[row * XW + col];
                        float v1 = acc[ni][half * 2 + 1] + xs[row * XW + col + 1];
                        asm("tanh.approx.f32 %0, %0;" : "+f"(v0));
                        asm("tanh.approx.f32 %0, %0;" : "+f"(v1));
                        *(__nv_bfloat162*)&hout[(size_t)(m0 + row) * HID + n0 + col] =
                            __floats2bfloat162_rn(v0, v1);
                    }
                }
                bar_sync(9, 128);        // wg0 stores complete + orders next xs gather
                if (wtid == 0) {
                    __threadfence();
                    atomicAdd(&g_ready[((t + 1) * GROUPS + grp) * 8 + 1 * 4 + mych], 1);
                }
            }
        }
    }

    // ---- fused logits / pred / loss ----
    if (tid == 0) {
        const int* f = &g_ready[(T_STEPS * GROUPS + grp) * 8];
        #pragma unroll
        for (int c = 0; c < 8; c++)
            while (ld_acq(f + c) < 4) { }
    }
    __syncthreads();

    for (int i = 0; i < 13; i++) {
        int j = i * 16 + warp;               // 200 samples per CTA
        if (j >= 200) break;
        int jj = nt * 200 + j;
        int t  = jj >> 5;
        int bl = jj & 31;
        int gw = t * BATCH + m0 + bl;
        int y  = y_idx[gw];
        const __nv_bfloat16* h = g_hidden + (size_t)(t + 1) * BATCH * HID
                               + (size_t)(m0 + bl) * HID;
        const float* wy = Wy + (size_t)y * HID;
        float acc = 0.f;
        #pragma unroll
        for (int p = 0; p < 4; p++) {
            int k = p * 256 + lane * 8;
            uint4 hv = *(const uint4*)(h + k);
            const float4* w4 = (const float4*)(wy + k);
            float4 w0 = w4[0], w1 = w4[1];
            const __nv_bfloat162* hb = (const __nv_bfloat162*)&hv;
            float2 f0 = __bfloat1622float2(hb[0]);
            float2 f1 = __bfloat1622float2(hb[1]);
            float2 f2 = __bfloat1622float2(hb[2]);
            float2 f3 = __bfloat1622float2(hb[3]);
            acc += f0.x * w0.x + f0.y * w0.y + f1.x * w0.z + f1.y * w0.w
                 + f2.x * w1.x + f2.y * w1.y + f3.x * w1.z + f3.y * w1.w;
        }
        #pragma unroll
        for (int o = 16; o; o >>= 1) acc += __shfl_xor_sync(0xffffffffu, acc, o);
        if (lane == 0) {
            float logit = acc + by[y];
            float pred = 1.f / (1.f + expf(-logit));
            float tr = truth[gw];
            float lsp = fminf(logit, 0.f)  - log1pf(expf(-fabsf(logit)));
            float lsn = fminf(-logit, 0.f) - log1pf(expf(-fabsf(logit)));
            out[gw] = pred;
            out[T_STEPS * BATCH + gw] = -(tr * lsp + (1.f - tr) * lsn);
        }
    }

    // ---- reset arrive counters for the next graph replay ----
    grid_barrier(tid);     // nobody still polling
    for (int i = blockIdx.x * THREADS + tid; i < (T_STEPS + 1) * GROUPS * 8;
         i += NCTA * THREADS)
        g_ready[i] = 0;
    __threadfence();
    grid_barrier(tid);     // resets visible before exit
}

// ---------------- launch ----------------
extern "C" void kernel_launch(void* const* d_in, const int* in_sizes, int n_in,
                              void* d_out, int out_size) {
    (void)in_sizes; (void)n_in; (void)out_size;
    const int*   x_idx   = (const int*)d_in[0];
    const int*   y_idx   = (const int*)d_in[1];
    const float* truth   = (const float*)d_in[2];
    const float* Wm      = (const float*)d_in[3];
    const float* bm      = (const float*)d_in[4];
    const float* Wx      = (const float*)d_in[5];
    const float* bx      = (const float*)d_in[6];
    const float* Wy      = (const float*)d_in[7];
    const float* by      = (const float*)d_in[8];
    // d_in[9] = W_start: multiplied by zeros -> unused
    const float* b_start = (const float*)d_in[10];
    float* out = (float*)d_out;

    // smem: 2 stream A tiles + xs + 4 partial buffers = ~148 KB
    const int smem_bytes = MT * SW * 2 + (MT * XW + 4 * RED1) * 4;
    cudaFuncSetAttribute(rnn_kernel, cudaFuncAttributeMaxDynamicSharedMemorySize, smem_bytes);
    rnn_kernel<<<NCTA, THREADS, smem_bytes>>>(x_idx, y_idx, truth, Wm, bm, Wx, bx,
                                              Wy, by, b_start, out);
}

// round 16
// speedup vs baseline: 1.0666x; 1.0553x over previous
#include <cuda_runtime.h>
#include <cuda_bf16.h>
#include <cstdint>
#include <cstddef>

#define T_STEPS 100
#define BATCH   256
#define HID     1024
#define N_IN    4096

#define NCTA    128
#define THREADS 512
#define GROUPS  8          // batch groups (32 rows each)
#define GSZ     16         // CTAs per group (N tiles)
#define MT      32         // batch rows per group
#define NT      64         // hidden cols per CTA
#define KC      256        // K chunk per warpgroup
#define SW      1032       // A smem row stride in bf16 (conflict-free ldmatrix)
#define XW      68         // xs row stride in floats
#define RSTRIDE 20         // red row stride in floats (16B-aligned, conflict-free)
#define REDSZ   (3 * 128 * RSTRIDE)   // floats per red buffer

// ---------------- device scratch ----------------
__device__ __nv_bfloat16 g_hidden[(size_t)(T_STEPS + 1) * BATCH * HID];
__device__ float         g_WxT[(size_t)N_IN * HID];             // Wx^T with (bm+bx) folded
__device__ int           g_ready[(T_STEPS + 1) * GROUPS * 4];   // per-chunk arrive counters
__device__ unsigned      g_count;                               // full-grid barrier
__device__ unsigned      g_gen;

// ---------------- helpers ----------------
__device__ __forceinline__ uint32_t smem_u32(const void* p) {
    return (uint32_t)__cvta_generic_to_shared(p);
}
__device__ __forceinline__ void ldmx4(uint32_t& r0, uint32_t& r1, uint32_t& r2, uint32_t& r3,
                                      uint32_t addr) {
    asm volatile("ldmatrix.sync.aligned.m8n8.x4.shared.b16 {%0,%1,%2,%3},[%4];\n"
                 : "=r"(r0), "=r"(r1), "=r"(r2), "=r"(r3) : "r"(addr));
}
__device__ __forceinline__ void mma16816(float* c, uint32_t a0, uint32_t a1, uint32_t a2,
                                         uint32_t a3, uint32_t b0, uint32_t b1) {
    asm volatile("mma.sync.aligned.m16n8k16.row.col.f32.bf16.bf16.f32 "
                 "{%0,%1,%2,%3},{%4,%5,%6,%7},{%8,%9},{%0,%1,%2,%3};\n"
                 : "+f"(c[0]), "+f"(c[1]), "+f"(c[2]), "+f"(c[3])
                 : "r"(a0), "r"(a1), "r"(a2), "r"(a3), "r"(b0), "r"(b1));
}
__device__ __forceinline__ void cp16(uint32_t dst, const void* src) {
    asm volatile("cp.async.cg.shared.global [%0],[%1],16;\n" :: "r"(dst), "l"(src));
}
__device__ __forceinline__ int ld_acq(const int* p) {
    int v;
    asm volatile("ld.acquire.gpu.global.b32 %0,[%1];" : "=r"(v) : "l"(p) : "memory");
    return v;
}
__device__ __forceinline__ void red_add_release(int* p, int v) {
    asm volatile("red.add.release.gpu.global.s32 [%0], %1;" :: "l"(p), "r"(v) : "memory");
}
__device__ __forceinline__ void bar_sync(int id, int cnt) {
    asm volatile("bar.sync %0, %1;" :: "r"(id), "r"(cnt) : "memory");
}
__device__ __forceinline__ void bar_arrive(int id, int cnt) {
    asm volatile("bar.arrive %0, %1;" :: "r"(id), "r"(cnt) : "memory");
}

__device__ __forceinline__ void grid_barrier(int tid) {
    __syncthreads();
    if (tid == 0) {
        __threadfence();
        unsigned gen = atomicAdd(&g_gen, 0u);
        unsigned old = atomicAdd(&g_count, 1u);
        if (old == NCTA - 1) {
            atomicExch(&g_count, 0u);
            __threadfence();
            atomicAdd(&g_gen, 1u);
        } else {
            while (*(volatile unsigned*)&g_gen == gen) { }
        }
        __threadfence();
    }
    __syncthreads();
}

// ---------------- single fused persistent kernel ----------------
__global__ void __launch_bounds__(THREADS, 1) rnn_kernel(
    const int* __restrict__ x_idx, const int* __restrict__ y_idx,
    const float* __restrict__ truth, const float* __restrict__ Wm,
    const float* __restrict__ bm, const float* __restrict__ Wx,
    const float* __restrict__ bx, const float* __restrict__ Wy,
    const float* __restrict__ by, const float* __restrict__ b_start,
    float* __restrict__ out) {
    extern __shared__ __align__(16) char smem_raw[];
    __nv_bfloat16* a_s = (__nv_bfloat16*)smem_raw;        // 32 x SW bf16 (full h tile)
    float*         xs  = (float*)(a_s + MT * SW);         // 32 x XW floats (+xpose stage)
    float*         red = xs + MT * XW;                    // 2 x REDSZ floats (dbuf partials)

    const int tid  = threadIdx.x;
    const int warp = tid >> 5, lane = tid & 31;
    const int wg   = warp >> 2;        // K chunk this warpgroup owns (0..3)
    const int nw   = warp & 3;         // N16 subtile within CTA (0..3)
    const int wtid = tid & 127;
    const int grp = blockIdx.x >> 4;   // batch group (8)
    const int nt  = blockIdx.x & 15;   // N tile within group (16)
    const int m0 = grp * MT;
    const int n0 = nt * NT;

    // ---- prologue: h0 = b_start broadcast ----
    for (int i = tid; i < MT * (NT / 2); i += THREADS) {
        int r = i >> 5, c2 = i & 31;
        __nv_bfloat162 v = __floats2bfloat162_rn(b_start[n0 + c2 * 2],
                                                 b_start[n0 + c2 * 2 + 1]);
        *(__nv_bfloat162*)&g_hidden[(size_t)(m0 + r) * HID + n0 + c2 * 2] = v;
    }

    // ---- prologue: transpose Wx slice with (bm+bx) folded ----
    {
        float (*tile)[33] = (float (*)[33])xs;
        int x0 = blockIdx.x * 32;
        int tx = lane, ty = warp;        // 32 x 16
        for (int yt = 0; yt < HID / 32; yt++) {
            int y0 = yt * 32;
            for (int i = ty; i < 32; i += 16)
                tile[i][tx] = Wx[(size_t)(y0 + i) * N_IN + x0 + tx];
            __syncthreads();
            for (int i = ty; i < 32; i += 16)
                g_WxT[(size_t)(x0 + i) * HID + y0 + tx] = tile[tx][i] + bm[y0 + tx] + bx[y0 + tx];
            __syncthreads();
        }
    }

    // ---- prologue: preload B fragments (Wm) into registers, ONCE ----
    // warp covers N16 (cols n0+nw*16..+16) x K256 (cols wg*256..+256)
    uint32_t breg[16][4];
    {
        const int nb = n0 + nw * 16 + (lane >> 2);
        const int kb = wg * KC + (lane & 3) * 2;
        #pragma unroll
        for (int kk = 0; kk < 16; kk++) {
            #pragma unroll
            for (int j = 0; j < 4; j++) {
                const float2 v = *(const float2*)&Wm[(size_t)(nb + (j >> 1) * 8) * HID
                                                     + kb + kk * 16 + (j & 1) * 8];
                ((__nv_bfloat162*)&breg[kk][j])[0] = __floats2bfloat162_rn(v.x, v.y);
            }
        }
    }
    __threadfence();
    grid_barrier(tid);   // WxT + h0 visible everywhere

    // A ldmatrix lane base (row = lane&15, k-half = lane>>4)
    const uint32_t a_lane = smem_u32(a_s) +
        (uint32_t)(((lane & 15) * SW + ((lane >> 4) << 3)) * 2);
    const int cp_row = wtid >> 2, cp_q4 = wtid & 3;
    const uint32_t cp_dst_row = smem_u32(a_s) + (uint32_t)(cp_row * SW * 2);
    const int mych = nt >> 2;            // the K-chunk this CTA's output belongs to

    // ---- mainloop: per-chunk dataflow, wgs 1-3 run ahead of wg0's tail ----
    for (int t = 0; t < T_STEPS; t++) {
        // wg0 gathers x projection (loads in flight during the flag spin below)
        if (wg == 0) {
            const int r = wtid >> 2, seg = wtid & 3;
            int x = x_idx[t * BATCH + m0 + r];
            const float4* src = (const float4*)&g_WxT[(size_t)x * HID + n0 + seg * 16];
            float4* dst = (float4*)&xs[r * XW + seg * 16];
            dst[0] = src[0]; dst[1] = src[1]; dst[2] = src[2]; dst[3] = src[3];
        }

        // gate THIS warpgroup's K-chunk on its 4 producers
        if (t > 0) {
            if (wtid == 0) {
                const int* f = &g_ready[(t * GROUPS + grp) * 4 + wg];
                while (ld_acq(f) < 4) { }
            }
            bar_sync(1 + wg, 128);
        }

        // issue the chunk as TWO 128-col sub-chunks (double-buffered commit groups)
        {
            const __nv_bfloat16* rowp = g_hidden + (size_t)t * BATCH * HID
                                      + (size_t)(m0 + cp_row) * HID;
            #pragma unroll
            for (int q = 0; q < 4; q++) {
                int c8 = wg * 32 + cp_q4 * 4 + q;            // units 0..15 of chunk
                cp16(cp_dst_row + (uint32_t)(c8 * 16), rowp + c8 * 8);
            }
            asm volatile("cp.async.commit_group;" ::: "memory");
            #pragma unroll
            for (int q = 0; q < 4; q++) {
                int c8 = wg * 32 + 16 + cp_q4 * 4 + q;       // units 16..31 of chunk
                cp16(cp_dst_row + (uint32_t)(c8 * 16), rowp + c8 * 8);
            }
            asm volatile("cp.async.commit_group;" ::: "memory");
        }

        float acc[2][2][4];
        #pragma unroll
        for (int i = 0; i < 2; i++)
            #pragma unroll
            for (int j = 0; j < 2; j++)
                acc[i][j][0] = acc[i][j][1] = acc[i][j][2] = acc[i][j][3] = 0.f;

        // MMA sub0 while sub1 is still in flight
        asm volatile("cp.async.wait_group 1;" ::: "memory");
        bar_sync(1 + wg, 128);
        #pragma unroll
        for (int kk = 0; kk < 8; kk++) {
            const uint32_t kbyte = (uint32_t)((wg * KC + kk * 16) * 2);
            uint32_t a0, a1, a2, a3, a4, a5, a6, a7;
            ldmx4(a0, a1, a2, a3, a_lane + kbyte);
            ldmx4(a4, a5, a6, a7, a_lane + (uint32_t)(16 * SW * 2) + kbyte);
            mma16816(acc[0][0], a0, a1, a2, a3, breg[kk][0], breg[kk][1]);
            mma16816(acc[0][1], a0, a1, a2, a3, breg[kk][2], breg[kk][3]);
            mma16816(acc[1][0], a4, a5, a6, a7, breg[kk][0], breg[kk][1]);
            mma16816(acc[1][1], a4, a5, a6, a7, breg[kk][2], breg[kk][3]);
        }
        asm volatile("cp.async.wait_group 0;" ::: "memory");
        bar_sync(1 + wg, 128);
        #pragma unroll
        for (int kk = 8; kk < 16; kk++) {
            const uint32_t kbyte = (uint32_t)((wg * KC + kk * 16) * 2);
            uint32_t a0, a1, a2, a3, a4, a5, a6, a7;
            ldmx4(a0, a1, a2, a3, a_lane + kbyte);
            ldmx4(a4, a5, a6, a7, a_lane + (uint32_t)(16 * SW * 2) + kbyte);
            mma16816(acc[0][0], a0, a1, a2, a3, breg[kk][0], breg[kk][1]);
            mma16816(acc[0][1], a0, a1, a2, a3, breg[kk][2], breg[kk][3]);
            mma16816(acc[1][0], a4, a5, a6, a7, breg[kk][0], breg[kk][1]);
            mma16816(acc[1][1], a4, a5, a6, a7, breg[kk][2], breg[kk][3]);
        }

        float* af = &acc[0][0][0];
        float* rbuf = red + (t & 1) * REDSZ;
        if (wg != 0) {
            // publish partials (aligned float4, conflict-free stride 20) and run ahead
            float4* dst = (float4*)&rbuf[((wg - 1) * 128 + wtid) * RSTRIDE];
            #pragma unroll
            for (int q = 0; q < 4; q++) dst[q] = ((const float4*)af)[q];
            bar_arrive(5, THREADS);
        } else {
            bar_sync(5, THREADS);   // wait for wgs 1-3 partials
            #pragma unroll
            for (int p = 0; p < 3; p++) {
                const float4* src = (const float4*)&rbuf[(p * 128 + wtid) * RSTRIDE];
                #pragma unroll
                for (int q = 0; q < 4; q++) {
                    float4 v = src[q];
                    af[q * 4 + 0] += v.x; af[q * 4 + 1] += v.y;
                    af[q * 4 + 2] += v.z; af[q * 4 + 3] += v.w;
                }
            }

            // epilogue: + xproj(+bias), tanh.approx, pack bf16, store h[t+1]
            __nv_bfloat16* hout = g_hidden + (size_t)(t + 1) * BATCH * HID;
            const int r_base = lane >> 2;
            const int c_base = (lane & 3) * 2;
            #pragma unroll
            for (int mi = 0; mi < 2; mi++) {
                #pragma unroll
                for (int ni = 0; ni < 2; ni++) {
                    int col = nw * 16 + ni * 8 + c_base;
                    #pragma unroll
                    for (int half = 0; half < 2; half++) {
                        int row = mi * 16 + r_base + half * 8;
                        float v0 = acc[mi][ni][half * 2 + 0] + xs[row * XW + col];
                        float v1 = acc[mi][ni][half * 2 + 1] + xs[row * XW + col + 1];
                        asm("tanh.approx.f32 %0, %0;" : "+f"(v0));
                        asm("tanh.approx.f32 %0, %0;" : "+f"(v1));
                        *(__nv_bfloat162*)&hout[(size_t)(m0 + row) * HID + n0 + col] =
                            __floats2bfloat162_rn(v0, v1);
                    }
                }
            }
            bar_sync(6, 128);       // wg0 stores complete (orders them before the release)
            if (wtid == 0) {
                // release-RED publish: cumulative release covers wg0 stores (via bar6),
                // no MEMBAR.GPU drain, no atomic return trip
                red_add_release(&g_ready[((t + 1) * GROUPS + grp) * 4 + mych], 1);
            }
        }
    }

    // ---- fused logits / pred / loss ----
    if (tid == 0) {
        const int* f = &g_ready[(T_STEPS * GROUPS + grp) * 4];
        #pragma unroll
        for (int c = 0; c < 4; c++)
            while (ld_acq(f + c) < 4) { }
    }
    __syncthreads();

    for (int i = 0; i < 13; i++) {
        int j = i * 16 + warp;               // 200 samples per CTA
        if (j >= 200) break;
        int jj = nt * 200 + j;
        int t  = jj >> 5;
        int bl = jj & 31;
        int gw = t * BATCH + m0 + bl;
        int y  = y_idx[gw];
        const __nv_bfloat16* h = g_hidden + (size_t)(t + 1) * BATCH * HID
                               + (size_t)(m0 + bl) * HID;
        const float* wy = Wy + (size_t)y * HID;
        float acc = 0.f;
        #pragma unroll
        for (int p = 0; p < 4; p++) {
            int k = p * 256 + lane * 8;
            uint4 hv = *(const uint4*)(h + k);
            const float4* w4 = (const float4*)(wy + k);
            float4 w0 = w4[0], w1 = w4[1];
            const __nv_bfloat162* hb = (const __nv_bfloat162*)&hv;
            float2 f0 = __bfloat1622float2(hb[0]);
            float2 f1 = __bfloat1622float2(hb[1]);
            float2 f2 = __bfloat1622float2(hb[2]);
            float2 f3 = __bfloat1622float2(hb[3]);
            acc += f0.x * w0.x + f0.y * w0.y + f1.x * w0.z + f1.y * w0.w
                 + f2.x * w1.x + f2.y * w1.y + f3.x * w1.z + f3.y * w1.w;
        }
        #pragma unroll
        for (int o = 16; o; o >>= 1) acc += __shfl_xor_sync(0xffffffffu, acc, o);
        if (lane == 0) {
            float logit = acc + by[y];
            float pred = 1.f / (1.f + expf(-logit));
            float tr = truth[gw];
            float lsp = fminf(logit, 0.f)  - log1pf(expf(-fabsf(logit)));
            float lsn = fminf(-logit, 0.f) - log1pf(expf(-fabsf(logit)));
            out[gw] = pred;
            out[T_STEPS * BATCH + gw] = -(tr * lsp + (1.f - tr) * lsn);
        }
    }

    // ---- reset arrive counters for the next graph replay ----
    grid_barrier(tid);     // nobody still polling
    for (int i = blockIdx.x * THREADS + tid; i < (T_STEPS + 1) * GROUPS * 4;
         i += NCTA * THREADS)
        g_ready[i] = 0;
    __threadfence();
    grid_barrier(tid);     // resets visible before exit
}

// ---------------- launch ----------------
extern "C" void kernel_launch(void* const* d_in, const int* in_sizes, int n_in,
                              void* d_out, int out_size) {
    (void)in_sizes; (void)n_in; (void)out_size;
    const int*   x_idx   = (const int*)d_in[0];
    const int*   y_idx   = (const int*)d_in[1];
    const float* truth   = (const float*)d_in[2];
    const float* Wm      = (const float*)d_in[3];
    const float* bm      = (const float*)d_in[4];
    const float* Wx      = (const float*)d_in[5];
    const float* bx      = (const float*)d_in[6];
    const float* Wy      = (const float*)d_in[7];
    const float* by      = (const float*)d_in[8];
    // d_in[9] = W_start: multiplied by zeros -> unused
    const float* b_start = (const float*)d_in[10];
    float* out = (float*)d_out;

    // smem: A tile + xs + double-buffered reduction = ~135 KB
    const int smem_bytes = MT * SW * 2 + (MT * XW + 2 * REDSZ) * 4;
    cudaFuncSetAttribute(rnn_kernel, cudaFuncAttributeMaxDynamicSharedMemorySize, smem_bytes);
    rnn_kernel<<<NCTA, THREADS, smem_bytes>>>(x_idx, y_idx, truth, Wm, bm, Wx, bx,
                                              Wy, by, b_start, out);
}

// round 17
// speedup vs baseline: 1.0926x; 1.0244x over previous
#include <cuda_runtime.h>
#include <cuda_bf16.h>
#include <cstdint>
#include <cstddef>

#define T_STEPS 100
#define BATCH   256
#define HID     1024
#define N_IN    4096

#define NCTA    128
#define THREADS 512
#define GROUPS  8          // batch groups (32 rows each)
#define GSZ     16         // CTAs per group (N tiles)
#define MT      32         // batch rows per group
#define NT      64         // hidden cols per CTA
#define KC      256        // K chunk per warpgroup
#define SW      1032       // A smem row stride in bf16 (conflict-free ldmatrix)
#define XW      68         // xs row stride in floats
#define RSTRIDE 20         // red row stride in floats (16B-aligned, conflict-free)
#define REDSZ   (3 * 128 * RSTRIDE)   // floats per red buffer

// ---------------- device scratch ----------------
__device__ __nv_bfloat16 g_hidden[(size_t)(T_STEPS + 1) * BATCH * HID];
__device__ float         g_WxT[(size_t)N_IN * HID];             // Wx^T with (bm+bx) folded
__device__ int           g_ready[(T_STEPS + 1) * GROUPS * 4];   // per-chunk arrive counters
__device__ unsigned      g_count;                               // full-grid barrier
__device__ unsigned      g_gen;

// ---------------- helpers ----------------
__device__ __forceinline__ uint32_t smem_u32(const void* p) {
    return (uint32_t)__cvta_generic_to_shared(p);
}
__device__ __forceinline__ void ldmx4(uint32_t& r0, uint32_t& r1, uint32_t& r2, uint32_t& r3,
                                      uint32_t addr) {
    asm volatile("ldmatrix.sync.aligned.m8n8.x4.shared.b16 {%0,%1,%2,%3},[%4];\n"
                 : "=r"(r0), "=r"(r1), "=r"(r2), "=r"(r3) : "r"(addr));
}
__device__ __forceinline__ void mma16816(float* c, uint32_t a0, uint32_t a1, uint32_t a2,
                                         uint32_t a3, uint32_t b0, uint32_t b1) {
    asm volatile("mma.sync.aligned.m16n8k16.row.col.f32.bf16.bf16.f32 "
                 "{%0,%1,%2,%3},{%4,%5,%6,%7},{%8,%9},{%0,%1,%2,%3};\n"
                 : "+f"(c[0]), "+f"(c[1]), "+f"(c[2]), "+f"(c[3])
                 : "r"(a0), "r"(a1), "r"(a2), "r"(a3), "r"(b0), "r"(b1));
}
__device__ __forceinline__ void cp16(uint32_t dst, const void* src) {
    asm volatile("cp.async.cg.shared.global [%0],[%1],16;\n" :: "r"(dst), "l"(src));
}
__device__ __forceinline__ int ld_acq(const int* p) {
    int v;
    asm volatile("ld.acquire.gpu.global.b32 %0,[%1];" : "=r"(v) : "l"(p) : "memory");
    return v;
}
__device__ __forceinline__ void red_add_release(int* p, int v) {
    asm volatile("red.add.release.gpu.global.s32 [%0], %1;" :: "l"(p), "r"(v) : "memory");
}
__device__ __forceinline__ void nsleep(unsigned ns) {
    asm volatile("nanosleep.u32 %0;" :: "r"(ns));
}
__device__ __forceinline__ void bar_sync(int id, int cnt) {
    asm volatile("bar.sync %0, %1;" :: "r"(id), "r"(cnt) : "memory");
}
__device__ __forceinline__ void bar_arrive(int id, int cnt) {
    asm volatile("bar.arrive %0, %1;" :: "r"(id), "r"(cnt) : "memory");
}

__device__ __forceinline__ void grid_barrier(int tid) {
    __syncthreads();
    if (tid == 0) {
        __threadfence();
        unsigned gen = atomicAdd(&g_gen, 0u);
        unsigned old = atomicAdd(&g_count, 1u);
        if (old == NCTA - 1) {
            atomicExch(&g_count, 0u);
            __threadfence();
            atomicAdd(&g_gen, 1u);
        } else {
            while (*(volatile unsigned*)&g_gen == gen) { }
        }
        __threadfence();
    }
    __syncthreads();
}

// ---------------- single fused persistent kernel ----------------
__global__ void __launch_bounds__(THREADS, 1) rnn_kernel(
    const int* __restrict__ x_idx, const int* __restrict__ y_idx,
    const float* __restrict__ truth, const float* __restrict__ Wm,
    const float* __restrict__ bm, const float* __restrict__ Wx,
    const float* __restrict__ bx, const float* __restrict__ Wy,
    const float* __restrict__ by, const float* __restrict__ b_start,
    float* __restrict__ out) {
    extern __shared__ __align__(16) char smem_raw[];
    __nv_bfloat16* a_s = (__nv_bfloat16*)smem_raw;        // 32 x SW bf16 (full h tile)
    float*         xs  = (float*)(a_s + MT * SW);         // 32 x XW floats (+xpose stage)
    float*         red = xs + MT * XW;                    // 2 x REDSZ floats (dbuf partials)

    const int tid  = threadIdx.x;
    const int warp = tid >> 5, lane = tid & 31;
    const int wg   = warp >> 2;        // K chunk this warpgroup owns (0..3)
    const int nw   = warp & 3;         // N16 subtile within CTA (0..3)
    const int wtid = tid & 127;
    const int grp = blockIdx.x >> 4;   // batch group (8)
    const int nt  = blockIdx.x & 15;   // N tile within group (16)
    const int m0 = grp * MT;
    const int n0 = nt * NT;
    // poller warp for wg sits on SMSP wg (warps 0,5,10,15) — one spinner per SMSP
    const bool is_poller = (warp == wg * 5) && (lane == 0);

    // ---- prologue: h0 = b_start broadcast ----
    for (int i = tid; i < MT * (NT / 2); i += THREADS) {
        int r = i >> 5, c2 = i & 31;
        __nv_bfloat162 v = __floats2bfloat162_rn(b_start[n0 + c2 * 2],
                                                 b_start[n0 + c2 * 2 + 1]);
        *(__nv_bfloat162*)&g_hidden[(size_t)(m0 + r) * HID + n0 + c2 * 2] = v;
    }

    // ---- prologue: transpose Wx slice with (bm+bx) folded ----
    {
        float (*tile)[33] = (float (*)[33])xs;
        int x0 = blockIdx.x * 32;
        int tx = lane, ty = warp;        // 32 x 16
        for (int yt = 0; yt < HID / 32; yt++) {
            int y0 = yt * 32;
            for (int i = ty; i < 32; i += 16)
                tile[i][tx] = Wx[(size_t)(y0 + i) * N_IN + x0 + tx];
            __syncthreads();
            for (int i = ty; i < 32; i += 16)
                g_WxT[(size_t)(x0 + i) * HID + y0 + tx] = tile[tx][i] + bm[y0 + tx] + bx[y0 + tx];
            __syncthreads();
        }
    }

    // ---- prologue: preload B fragments (Wm) into registers, ONCE ----
    // warp covers N16 (cols n0+nw*16..+16) x K256 (cols wg*256..+256)
    uint32_t breg[16][4];
    {
        const int nb = n0 + nw * 16 + (lane >> 2);
        const int kb = wg * KC + (lane & 3) * 2;
        #pragma unroll
        for (int kk = 0; kk < 16; kk++) {
            #pragma unroll
            for (int j = 0; j < 4; j++) {
                const float2 v = *(const float2*)&Wm[(size_t)(nb + (j >> 1) * 8) * HID
                                                     + kb + kk * 16 + (j & 1) * 8];
                ((__nv_bfloat162*)&breg[kk][j])[0] = __floats2bfloat162_rn(v.x, v.y);
            }
        }
    }
    __threadfence();
    grid_barrier(tid);   // WxT + h0 visible everywhere

    // A ldmatrix lane base (row = lane&15, k-half = lane>>4)
    const uint32_t a_lane = smem_u32(a_s) +
        (uint32_t)(((lane & 15) * SW + ((lane >> 4) << 3)) * 2);
    const int cp_row = wtid >> 2, cp_q4 = wtid & 3;
    const uint32_t cp_dst_row = smem_u32(a_s) + (uint32_t)(cp_row * SW * 2);
    const int mych = nt >> 2;            // the K-chunk this CTA's output belongs to

    // ---- mainloop: per-chunk dataflow, wgs 1-3 run ahead of wg0's tail ----
    for (int t = 0; t < T_STEPS; t++) {
        // wg0 gathers x projection (loads in flight during the flag spin below)
        if (wg == 0) {
            const int r = wtid >> 2, seg = wtid & 3;
            int x = x_idx[t * BATCH + m0 + r];
            const float4* src = (const float4*)&g_WxT[(size_t)x * HID + n0 + seg * 16];
            float4* dst = (float4*)&xs[r * XW + seg * 16];
            dst[0] = src[0]; dst[1] = src[1]; dst[2] = src[2]; dst[3] = src[3];
        }

        // gate THIS warpgroup's K-chunk on its 4 producers (backoff spin, 1 poller/SMSP)
        if (t > 0) {
            if (is_poller) {
                const int* f = &g_ready[(t * GROUPS + grp) * 4 + wg];
                while (ld_acq(f) < 4) { nsleep(64); }
            }
            bar_sync(1 + wg, 128);
        }

        // issue the chunk as TWO 128-col sub-chunks (double-buffered commit groups)
        {
            const __nv_bfloat16* rowp = g_hidden + (size_t)t * BATCH * HID
                                      + (size_t)(m0 + cp_row) * HID;
            #pragma unroll
            for (int q = 0; q < 4; q++) {
                int c8 = wg * 32 + cp_q4 * 4 + q;            // units 0..15 of chunk
                cp16(cp_dst_row + (uint32_t)(c8 * 16), rowp + c8 * 8);
            }
            asm volatile("cp.async.commit_group;" ::: "memory");
            #pragma unroll
            for (int q = 0; q < 4; q++) {
                int c8 = wg * 32 + 16 + cp_q4 * 4 + q;       // units 16..31 of chunk
                cp16(cp_dst_row + (uint32_t)(c8 * 16), rowp + c8 * 8);
            }
            asm volatile("cp.async.commit_group;" ::: "memory");
        }

        float acc[2][2][4];
        #pragma unroll
        for (int i = 0; i < 2; i++)
            #pragma unroll
            for (int j = 0; j < 2; j++)
                acc[i][j][0] = acc[i][j][1] = acc[i][j][2] = acc[i][j][3] = 0.f;

        // MMA sub0 while sub1 is still in flight
        asm volatile("cp.async.wait_group 1;" ::: "memory");
        bar_sync(1 + wg, 128);
        #pragma unroll
        for (int kk = 0; kk < 8; kk++) {
            const uint32_t kbyte = (uint32_t)((wg * KC + kk * 16) * 2);
            uint32_t a0, a1, a2, a3, a4, a5, a6, a7;
            ldmx4(a0, a1, a2, a3, a_lane + kbyte);
            ldmx4(a4, a5, a6, a7, a_lane + (uint32_t)(16 * SW * 2) + kbyte);
            mma16816(acc[0][0], a0, a1, a2, a3, breg[kk][0], breg[kk][1]);
            mma16816(acc[0][1], a0, a1, a2, a3, breg[kk][2], breg[kk][3]);
            mma16816(acc[1][0], a4, a5, a6, a7, breg[kk][0], breg[kk][1]);
            mma16816(acc[1][1], a4, a5, a6, a7, breg[kk][2], breg[kk][3]);
        }
        asm volatile("cp.async.wait_group 0;" ::: "memory");
        bar_sync(1 + wg, 128);
        #pragma unroll
        for (int kk = 8; kk < 16; kk++) {
            const uint32_t kbyte = (uint32_t)((wg * KC + kk * 16) * 2);
            uint32_t a0, a1, a2, a3, a4, a5, a6, a7;
            ldmx4(a0, a1, a2, a3, a_lane + kbyte);
            ldmx4(a4, a5, a6, a7, a_lane + (uint32_t)(16 * SW * 2) + kbyte);
            mma16816(acc[0][0], a0, a1, a2, a3, breg[kk][0], breg[kk][1]);
            mma16816(acc[0][1], a0, a1, a2, a3, breg[kk][2], breg[kk][3]);
            mma16816(acc[1][0], a4, a5, a6, a7, breg[kk][0], breg[kk][1]);
            mma16816(acc[1][1], a4, a5, a6, a7, breg[kk][2], breg[kk][3]);
        }

        float* af = &acc[0][0][0];
        float* rbuf = red + (t & 1) * REDSZ;
        if (wg != 0) {
            // publish partials (aligned float4, conflict-free stride 20) and run ahead
            float4* dst = (float4*)&rbuf[((wg - 1) * 128 + wtid) * RSTRIDE];
            #pragma unroll
            for (int q = 0; q < 4; q++) dst[q] = ((const float4*)af)[q];
            bar_arrive(5, THREADS);
        } else {
            bar_sync(5, THREADS);   // wait for wgs 1-3 partials
            #pragma unroll
            for (int p = 0; p < 3; p++) {
                const float4* src = (const float4*)&rbuf[(p * 128 + wtid) * RSTRIDE];
                #pragma unroll
                for (int q = 0; q < 4; q++) {
                    float4 v = src[q];
                    af[q * 4 + 0] += v.x; af[q * 4 + 1] += v.y;
                    af[q * 4 + 2] += v.z; af[q * 4 + 3] += v.w;
                }
            }

            // epilogue: + xproj(+bias), tanh.approx, pack bf16, store h[t+1]
            __nv_bfloat16* hout = g_hidden + (size_t)(t + 1) * BATCH * HID;
            const int r_base = lane >> 2;
            const int c_base = (lane & 3) * 2;
            #pragma unroll
            for (int mi = 0; mi < 2; mi++) {
                #pragma unroll
                for (int ni = 0; ni < 2; ni++) {
                    int col = nw * 16 + ni * 8 + c_base;
                    #pragma unroll
                    for (int half = 0; half < 2; half++) {
                        int row = mi * 16 + r_base + half * 8;
                        float v0 = acc[mi][ni][half * 2 + 0] + xs[row * XW + col];
                        float v1 = acc[mi][ni][half * 2 + 1] + xs[row * XW + col + 1];
                        asm("tanh.approx.f32 %0, %0;" : "+f"(v0));
                        asm("tanh.approx.f32 %0, %0;" : "+f"(v1));
                        *(__nv_bfloat162*)&hout[(size_t)(m0 + row) * HID + n0 + col] =
                            __floats2bfloat162_rn(v0, v1);
                    }
                }
            }
            bar_sync(6, 128);       // wg0 stores complete (orders them before the release)
            if (wtid == 0) {
                // release-RED publish: cumulative release covers wg0 stores (via bar6)
                red_add_release(&g_ready[((t + 1) * GROUPS + grp) * 4 + mych], 1);
            }
        }
    }

    // ---- fused logits / pred / loss ----
    if (tid == 0) {
        const int* f = &g_ready[(T_STEPS * GROUPS + grp) * 4];
        #pragma unroll
        for (int c = 0; c < 4; c++)
            while (ld_acq(f + c) < 4) { nsleep(128); }
    }
    __syncthreads();

    for (int i = 0; i < 13; i++) {
        int j = i * 16 + warp;               // 200 samples per CTA
        if (j >= 200) break;
        int jj = nt * 200 + j;
        int t  = jj >> 5;
        int bl = jj & 31;
        int gw = t * BATCH + m0 + bl;
        int y  = y_idx[gw];
        const __nv_bfloat16* h = g_hidden + (size_t)(t + 1) * BATCH * HID
                               + (size_t)(m0 + bl) * HID;
        const float* wy = Wy + (size_t)y * HID;
        float acc = 0.f;
        #pragma unroll
        for (int p = 0; p < 4; p++) {
            int k = p * 256 + lane * 8;
            uint4 hv = *(const uint4*)(h + k);
            const float4* w4 = (const float4*)(wy + k);
            float4 w0 = w4[0], w1 = w4[1];
            const __nv_bfloat162* hb = (const __nv_bfloat162*)&hv;
            float2 f0 = __bfloat1622float2(hb[0]);
            float2 f1 = __bfloat1622float2(hb[1]);
            float2 f2 = __bfloat1622float2(hb[2]);
            float2 f3 = __bfloat1622float2(hb[3]);
            acc += f0.x * w0.x + f0.y * w0.y + f1.x * w0.z + f1.y * w0.w
                 + f2.x * w1.x + f2.y * w1.y + f3.x * w1.z + f3.y * w1.w;
        }
        #pragma unroll
        for (int o = 16; o; o >>= 1) acc += __shfl_xor_sync(0xffffffffu, acc, o);
        if (lane == 0) {
            float logit = acc + by[y];
            float pred = 1.f / (1.f + expf(-logit));
            float tr = truth[gw];
            float lsp = fminf(logit, 0.f)  - log1pf(expf(-fabsf(logit)));
            float lsn = fminf(-logit, 0.f) - log1pf(expf(-fabsf(logit)));
            out[gw] = pred;
            out[T_STEPS * BATCH + gw] = -(tr * lsp + (1.f - tr) * lsn);
        }
    }

    // ---- reset arrive counters for the next graph replay ----
    grid_barrier(tid);     // nobody still polling
    for (int i = blockIdx.x * THREADS + tid; i < (T_STEPS + 1) * GROUPS * 4;
         i += NCTA * THREADS)
        g_ready[i] = 0;
    __threadfence();
    grid_barrier(tid);     // resets visible before exit
}

// ---------------- launch ----------------
extern "C" void kernel_launch(void* const* d_in, const int* in_sizes, int n_in,
                              void* d_out, int out_size) {
    (void)in_sizes; (void)n_in; (void)out_size;
    const int*   x_idx   = (const int*)d_in[0];
    const int*   y_idx   = (const int*)d_in[1];
    const float* truth   = (const float*)d_in[2];
    const float* Wm      = (const float*)d_in[3];
    const float* bm      = (const float*)d_in[4];
    const float* Wx      = (const float*)d_in[5];
    const float* bx      = (const float*)d_in[6];
    const float* Wy      = (const float*)d_in[7];
    const float* by      = (const float*)d_in[8];
    // d_in[9] = W_start: multiplied by zeros -> unused
    const float* b_start = (const float*)d_in[10];
    float* out = (float*)d_out;

    // smem: A tile + xs + double-buffered reduction = ~135 KB
    const int smem_bytes = MT * SW * 2 + (MT * XW + 2 * REDSZ) * 4;
    cudaFuncSetAttribute(rnn_kernel, cudaFuncAttributeMaxDynamicSharedMemorySize, smem_bytes);
    rnn_kernel<<<NCTA, THREADS, smem_bytes>>>(x_idx, y_idx, truth, Wm, bm, Wx, bx,
                                              Wy, by, b_start, out);
}